// round 10
// baseline (speedup 1.0000x reference)
#include <cuda_runtime.h>
#include <cuda_fp16.h>

#define NROWS 16384   // B*T
#define EDIM  1024
#define DDIM  64
#define BSZ   8
#define TSEQ  2048
#define QT    64      // attention q-tile rows
#define KT    64      // attention kv-tile rows
#define CKT   8       // kv tiles per chunk (512 keys)
#define NJOB  80      // jobs per batch = sum ceil((qt+1)/8), qt=0..31

// Projected tensors, fp16. q pre-scaled by 0.125. v stored transposed
// per batch: g_vt[b][d][t].
__device__ __align__(16) __half g_qh[NROWS * DDIM];
__device__ __align__(16) __half g_kh[NROWS * DDIM];
__device__ __align__(16) __half g_vt[BSZ * DDIM * TSEQ];

// Weights converted to fp16 once: [w][64][1024], w in {q,k,v}
__device__ __align__(16) __half g_wh[3 * DDIM * EDIM];

// Split-KV partials: [b][qt][chunk] -> unnormalized O (64x64), row m, row l
__device__ float g_part[(size_t)BSZ * 32 * 4 * 64 * 64];   // 16.8 MB
__device__ float g_pm[BSZ * 32 * 4 * 64];
__device__ float g_pl[BSZ * 32 * 4 * 64];

// ---------------------------------------------------------------------------
// helpers
// ---------------------------------------------------------------------------
__device__ __forceinline__ unsigned packh2(float lo, float hi) {
    __half2 h = __floats2half2_rn(lo, hi);
    return *reinterpret_cast<unsigned*>(&h);
}

__device__ __forceinline__ void mma16(float c[4],
                                      unsigned a0, unsigned a1,
                                      unsigned a2, unsigned a3,
                                      unsigned b0, unsigned b1) {
    asm volatile(
        "mma.sync.aligned.m16n8k16.row.col.f32.f16.f16.f32 "
        "{%0,%1,%2,%3},{%4,%5,%6,%7},{%8,%9},{%0,%1,%2,%3};\n"
        : "+f"(c[0]), "+f"(c[1]), "+f"(c[2]), "+f"(c[3])
        : "r"(a0), "r"(a1), "r"(a2), "r"(a3), "r"(b0), "r"(b1));
}

__device__ __forceinline__ void cpa16(void* dst_smem, const void* src) {
    unsigned d = (unsigned)__cvta_generic_to_shared(dst_smem);
    asm volatile("cp.async.cg.shared.global [%0], [%1], 16;\n"
                 :: "r"(d), "l"(src));
}
__device__ __forceinline__ void cpa_commit() {
    asm volatile("cp.async.commit_group;\n" ::: "memory");
}
template <int N>
__device__ __forceinline__ void cpa_wait() {
    asm volatile("cp.async.wait_group %0;\n" :: "n"(N) : "memory");
}

// exp(x) for x <= ~1, FMA-pipe only. deg-5 poly, rel err < 3e-6.
__device__ __forceinline__ float fast_exp(float x) {
    float t = x * 1.4426950408889634f;
    t = fmaxf(t, -126.0f);
    float tr = t + 12582912.0f;
    float fl = tr - 12582912.0f;
    float f  = t - fl;
    float p = 1.3333558146e-3f;
    p = fmaf(p, f, 9.6181291076e-3f);
    p = fmaf(p, f, 5.5504108664e-2f);
    p = fmaf(p, f, 2.4022650696e-1f);
    p = fmaf(p, f, 6.9314718056e-1f);
    p = fmaf(p, f, 1.0f);
    int n = __float_as_int(tr) - 0x4B400000;
    float s = __int_as_float((n + 127) << 23);
    return p * s;
}

// ---------------------------------------------------------------------------
// Weight conversion: fp32 -> fp16, once.
// ---------------------------------------------------------------------------
__global__ __launch_bounds__(256) void conv_w(
    const float* __restrict__ Wq,
    const float* __restrict__ Wk,
    const float* __restrict__ Wv)
{
    int idx = blockIdx.x * blockDim.x + threadIdx.x;   // float4 index
    int w   = idx >> 14;
    int rem = idx & 16383;
    const float* W = (w == 0) ? Wq : (w == 1) ? Wk : Wv;
    float4 v = *(const float4*)&W[rem * 4];
    __half2 h0 = __floats2half2_rn(v.x, v.y);
    __half2 h1 = __floats2half2_rn(v.z, v.w);
    uint2 u = make_uint2(*(unsigned*)&h0, *(unsigned*)&h1);
    *(uint2*)&g_wh[(size_t)w * DDIM * EDIM + rem * 4] = u;
}

// ---------------------------------------------------------------------------
// Merged projection GEMM: 128-row slab, 512 threads (16 warps: 4m x 4n),
// warptile = 32 rows x 16 cols x 3 outputs (48 acc regs). fp16 weights,
// 3-stage cp.async, ONE barrier per chunk. Grid = 128 blocks, 16 warps/SM.
// Stage = 128x36 f32 (x) + 3x64x40 f16 (W) = 33792 B; 3 stages = 101376 B.
// ---------------------------------------------------------------------------
#define PROJ_XS_F    (128 * 36)                           // floats
#define PROJ_WS_H    (3 * 64 * 40)                        // halves
#define PROJ_STAGE_B (PROJ_XS_F * 4 + PROJ_WS_H * 2)      // 33792 bytes
#define PROJ_SMEM    (3 * PROJ_STAGE_B)                   // 101376

__global__ __launch_bounds__(512, 1) void proj_mma(
    const float* __restrict__ x)
{
    extern __shared__ char dynb[];

    const int tid  = threadIdx.x;
    const int lane = tid & 31;
    const int wid  = tid >> 5;
    const int wm   = wid & 3;       // 4 m-warps (32 rows each)
    const int wn   = wid >> 2;      // 4 n-warps (16 cols each)
    const int r    = lane >> 2;
    const int cq   = lane & 3;
    const int m0   = blockIdx.x * 128;

    auto prefetch = [&](int kc, int s) {
        char* stage = dynb + (size_t)s * PROJ_STAGE_B;
        float  (*xs)[36]     = (float(*)[36])stage;
        __half (*ws)[64][40] = (__half(*)[64][40])(stage + PROJ_XS_F * 4);
        int k0 = kc * 32;
#pragma unroll
        for (int i = 0; i < 2; i++) {
            int slot = tid + i * 512;        // 1024 chunks (128 rows x 8)
            int m = slot >> 3, j = slot & 7;
            cpa16(&xs[m][4 * j], &x[(size_t)(m0 + m) * EDIM + k0 + 4 * j]);
        }
#pragma unroll
        for (int i = 0; i < 2; i++) {
            int slot = tid + i * 512;        // 768 chunks (3x64 rows x 4)
            if (slot < 768) {
                int w = slot >> 8, rem = slot & 255;
                int d = rem >> 2, j = rem & 3;
                cpa16(&ws[w][d][8 * j],
                      &g_wh[(size_t)w * DDIM * EDIM + (size_t)d * EDIM + k0 + 8 * j]);
            }
        }
        cpa_commit();
    };

    float acc[3][2][2][4] = {};   // [output][mt][nt][reg]

    prefetch(0, 0);
    prefetch(1, 1);
    for (int kc = 0; kc < 32; kc++) {
        const int s = kc % 3;
        cpa_wait<1>();                 // chunk kc arrived
        __syncthreads();               // all warps done with slot (kc-1)%3
        if (kc + 2 < 32) prefetch(kc + 2, (kc + 2) % 3);

        char* stage = dynb + (size_t)s * PROJ_STAGE_B;
        float  (*xs)[36]     = (float(*)[36])stage;
        __half (*ws)[64][40] = (__half(*)[64][40])(stage + PROJ_XS_F * 4);

#pragma unroll
        for (int ks = 0; ks < 2; ks++) {
            int k = ks * 16;
            unsigned a[2][4];
#pragma unroll
            for (int mt = 0; mt < 2; mt++) {
                int rb = wm * 32 + mt * 16;
                float2 x0 = *(float2*)&xs[rb + r][k + 2 * cq];
                float2 x1 = *(float2*)&xs[rb + r + 8][k + 2 * cq];
                float2 x2 = *(float2*)&xs[rb + r][k + 2 * cq + 8];
                float2 x3 = *(float2*)&xs[rb + r + 8][k + 2 * cq + 8];
                a[mt][0] = packh2(x0.x, x0.y);
                a[mt][1] = packh2(x1.x, x1.y);
                a[mt][2] = packh2(x2.x, x2.y);
                a[mt][3] = packh2(x3.x, x3.y);
            }
#pragma unroll
            for (int w = 0; w < 3; w++)
#pragma unroll
                for (int nt = 0; nt < 2; nt++) {
                    int nb = wn * 16 + nt * 8 + r;
                    unsigned b0 = *(const unsigned*)&ws[w][nb][k + 2 * cq];
                    unsigned b1 = *(const unsigned*)&ws[w][nb][k + 2 * cq + 8];
                    mma16(acc[w][0][nt], a[0][0], a[0][1], a[0][2], a[0][3], b0, b1);
                    mma16(acc[w][1][nt], a[1][0], a[1][1], a[1][2], a[1][3], b0, b1);
                }
        }
    }

    // epilogue: q (scaled), k natural fp16; v transposed fp16
#pragma unroll
    for (int mt = 0; mt < 2; mt++)
#pragma unroll
        for (int nt = 0; nt < 2; nt++) {
            int row = m0 + wm * 32 + mt * 16 + r;
            int col = wn * 16 + nt * 8 + 2 * cq;
            {
                float* a = acc[0][mt][nt];
                *(__half2*)&g_qh[(size_t)row * DDIM + col] =
                    __floats2half2_rn(a[0] * 0.125f, a[1] * 0.125f);
                *(__half2*)&g_qh[(size_t)(row + 8) * DDIM + col] =
                    __floats2half2_rn(a[2] * 0.125f, a[3] * 0.125f);
            }
            {
                float* a = acc[1][mt][nt];
                *(__half2*)&g_kh[(size_t)row * DDIM + col] =
                    __floats2half2_rn(a[0], a[1]);
                *(__half2*)&g_kh[(size_t)(row + 8) * DDIM + col] =
                    __floats2half2_rn(a[2], a[3]);
            }
            {
                float* a = acc[2][mt][nt];
                int bb = row >> 11;
                int tt = row & 2047;
                size_t vb = (size_t)bb * DDIM * TSEQ;
                g_vt[vb + (size_t)col * TSEQ + tt]           = __float2half_rn(a[0]);
                g_vt[vb + (size_t)(col + 1) * TSEQ + tt]     = __float2half_rn(a[1]);
                g_vt[vb + (size_t)col * TSEQ + tt + 8]       = __float2half_rn(a[2]);
                g_vt[vb + (size_t)(col + 1) * TSEQ + tt + 8] = __float2half_rn(a[3]);
            }
        }
}

// ---------------------------------------------------------------------------
// Split-KV flash attention (R6-proven loop: 2-stage, 2 barriers/tile).
// Job = (batch, q-tile, kv-chunk of <=8 KT-tiles). 640 blocks.
// ---------------------------------------------------------------------------
__global__ __launch_bounds__(128, 4) void attn_split(float* __restrict__ out)
{
    __shared__ __align__(16) __half Ks[2][KT][72];
    __shared__ __align__(16) __half Vt[2][DDIM][72];

    const int tid  = threadIdx.x;
    const int lane = tid & 31;
    const int w    = tid >> 5;
    const int r    = lane >> 2;
    const int cq   = lane & 3;
    const int b    = blockIdx.y;

    // job decode (reversed so 8-tile chunks launch first)
    const int j = NJOB - 1 - blockIdx.x;
    int qt, ck;
    if (j < 8)       { qt = j;                   ck = 0; }
    else if (j < 24) { qt = 8  + ((j - 8)  >> 1); ck = (j - 8)  & 1; }
    else if (j < 48) { qt = 16 + (j - 24) / 3;    ck = (j - 24) % 3; }
    else             { qt = 24 + ((j - 48) >> 2); ck = (j - 48) & 3; }
    const int nch  = qt / CKT + 1;
    const int kbeg = ck * CKT;
    const int kend = min(kbeg + CKT, qt + 1);

    const int q0 = qt * QT;
    const size_t base  = (size_t)b * TSEQ * DDIM;
    const size_t vbase = (size_t)b * DDIM * TSEQ;

    auto prefetch = [&](int kt, int s) {
        int k0 = kt * KT;
#pragma unroll
        for (int i = 0; i < 4; i++) {
            int slot = tid + i * 128;
            int m = slot >> 3, jj = slot & 7;
            cpa16(&Ks[s][m][8 * jj], &g_kh[base + (size_t)(k0 + m) * DDIM + 8 * jj]);
            cpa16(&Vt[s][m][8 * jj], &g_vt[vbase + (size_t)m * TSEQ + k0 + 8 * jj]);
        }
        cpa_commit();
    };

    // Q fragments (fp16, pre-scaled)
    unsigned qa[4][4];
    {
        const __half* q0p = &g_qh[base + (size_t)(q0 + 16 * w + r) * DDIM];
        const __half* q1p = q0p + 8 * DDIM;
#pragma unroll
        for (int kc = 0; kc < 4; kc++) {
            int c = 16 * kc + 2 * cq;
            qa[kc][0] = *(const unsigned*)&q0p[c];
            qa[kc][1] = *(const unsigned*)&q1p[c];
            qa[kc][2] = *(const unsigned*)&q0p[c + 8];
            qa[kc][3] = *(const unsigned*)&q1p[c + 8];
        }
    }

    float O[8][4] = {};
    float mA = -1e30f, mB = -1e30f, lA = 0.f, lB = 0.f;

    prefetch(kbeg, 0);

    for (int kt = kbeg; kt < kend; kt++) {
        const int s  = (kt - kbeg) & 1;
        const int k0 = kt * KT;
        __syncthreads();
        if (kt + 1 < kend) { prefetch(kt + 1, s ^ 1); cpa_wait<1>(); }
        else               { cpa_wait<0>(); }
        __syncthreads();

        // ---- S = Q * K^T ----
        float sacc[8][4] = {};
#pragma unroll
        for (int kc = 0; kc < 4; kc++) {
#pragma unroll
            for (int nt = 0; nt < 8; nt++) {
                unsigned b0 = *(const unsigned*)&Ks[s][nt * 8 + r][16 * kc + 2 * cq];
                unsigned b1 = *(const unsigned*)&Ks[s][nt * 8 + r][16 * kc + 2 * cq + 8];
                mma16(sacc[nt], qa[kc][0], qa[kc][1], qa[kc][2], qa[kc][3], b0, b1);
            }
        }

        // ---- causal mask (diagonal tile only) ----
        if (kt == qt) {
            int rowg = q0 + 16 * w + r;
#pragma unroll
            for (int nt = 0; nt < 8; nt++) {
                int col = k0 + nt * 8 + 2 * cq;
                if (col     > rowg)     sacc[nt][0] = -1e30f;
                if (col + 1 > rowg)     sacc[nt][1] = -1e30f;
                if (col     > rowg + 8) sacc[nt][2] = -1e30f;
                if (col + 1 > rowg + 8) sacc[nt][3] = -1e30f;
            }
        }

        // ---- warp-local online softmax; P packed in registers ----
        unsigned phA[8], phB[8];
        {
            float pmA = -1e30f, pmB = -1e30f;
#pragma unroll
            for (int nt = 0; nt < 8; nt++) {
                pmA = fmaxf(pmA, fmaxf(sacc[nt][0], sacc[nt][1]));
                pmB = fmaxf(pmB, fmaxf(sacc[nt][2], sacc[nt][3]));
            }
            pmA = fmaxf(pmA, __shfl_xor_sync(0xffffffffu, pmA, 1));
            pmA = fmaxf(pmA, __shfl_xor_sync(0xffffffffu, pmA, 2));
            pmB = fmaxf(pmB, __shfl_xor_sync(0xffffffffu, pmB, 1));
            pmB = fmaxf(pmB, __shfl_xor_sync(0xffffffffu, pmB, 2));
            float nmA = fmaxf(mA, pmA), nmB = fmaxf(mB, pmB);
            float alA = fast_exp(mA - nmA), alB = fast_exp(mB - nmB);
            mA = nmA; mB = nmB;

            float sA = 0.f, sB = 0.f;
#pragma unroll
            for (int nt = 0; nt < 8; nt++) {
                float p0 = fast_exp(sacc[nt][0] - nmA);
                float p1 = fast_exp(sacc[nt][1] - nmA);
                float p2 = fast_exp(sacc[nt][2] - nmB);
                float p3 = fast_exp(sacc[nt][3] - nmB);
                sA += p0 + p1; sB += p2 + p3;
                phA[nt] = packh2(p0, p1);
                phB[nt] = packh2(p2, p3);
            }
            sA += __shfl_xor_sync(0xffffffffu, sA, 1);
            sA += __shfl_xor_sync(0xffffffffu, sA, 2);
            sB += __shfl_xor_sync(0xffffffffu, sB, 1);
            sB += __shfl_xor_sync(0xffffffffu, sB, 2);
            lA = lA * alA + sA;
            lB = lB * alB + sB;
#pragma unroll
            for (int nt = 0; nt < 8; nt++) {
                O[nt][0] *= alA; O[nt][1] *= alA;
                O[nt][2] *= alB; O[nt][3] *= alB;
            }
        }

        // ---- O += P * V ----
#pragma unroll
        for (int kc = 0; kc < 4; kc++) {
            unsigned a0 = phA[2 * kc],     a1 = phB[2 * kc];
            unsigned a2 = phA[2 * kc + 1], a3 = phB[2 * kc + 1];
#pragma unroll
            for (int nt = 0; nt < 8; nt++) {
                unsigned b0 = *(const unsigned*)&Vt[s][nt * 8 + r][16 * kc + 2 * cq];
                unsigned b1 = *(const unsigned*)&Vt[s][nt * 8 + r][16 * kc + 2 * cq + 8];
                mma16(O[nt], a0, a1, a2, a3, b0, b1);
            }
        }
    }

    // ---- epilogue ----
    if (nch == 1) {
        float ilA = 1.f / lA, ilB = 1.f / lB;
        int rowg = q0 + 16 * w + r;
#pragma unroll
        for (int nt = 0; nt < 8; nt++) {
            int col = nt * 8 + 2 * cq;
            *(float2*)&out[base + (size_t)rowg * DDIM + col] =
                make_float2(O[nt][0] * ilA, O[nt][1] * ilA);
            *(float2*)&out[base + (size_t)(rowg + 8) * DDIM + col] =
                make_float2(O[nt][2] * ilB, O[nt][3] * ilB);
        }
    } else {
        const size_t slot = ((size_t)b * 32 + qt) * 4 + ck;
        float* P = g_part + slot * (64 * 64);
        int rowL = 16 * w + r;
#pragma unroll
        for (int nt = 0; nt < 8; nt++) {
            int col = nt * 8 + 2 * cq;
            *(float2*)&P[(size_t)rowL * 64 + col]       = make_float2(O[nt][0], O[nt][1]);
            *(float2*)&P[(size_t)(rowL + 8) * 64 + col] = make_float2(O[nt][2], O[nt][3]);
        }
        if (cq == 0) {
            g_pm[slot * 64 + rowL]     = mA;
            g_pl[slot * 64 + rowL]     = lA;
            g_pm[slot * 64 + rowL + 8] = mB;
            g_pl[slot * 64 + rowL + 8] = lB;
        }
    }
}

// ---------------------------------------------------------------------------
// Merge kernel: combine 2..4 KV-chunk partials for q-tiles qt >= 8.
// Grid (24, 8), 512 threads: thread owns one row x 8 d-cols.
// ---------------------------------------------------------------------------
__global__ __launch_bounds__(512) void attn_merge(float* __restrict__ out)
{
    const int qt  = 8 + blockIdx.x;
    const int b   = blockIdx.y;
    const int nch = qt / CKT + 1;
    const int tid = threadIdx.x;
    const int row = tid >> 3;
    const int cg  = (tid & 7) * 8;

    const size_t slot0 = ((size_t)b * 32 + qt) * 4;

    float m[4], l[4];
    float M = -1e30f;
#pragma unroll
    for (int c = 0; c < 4; c++) {
        if (c < nch) {
            m[c] = g_pm[(slot0 + c) * 64 + row];
            l[c] = g_pl[(slot0 + c) * 64 + row];
            M = fmaxf(M, m[c]);
        }
    }
    float L = 0.f, sc[4];
#pragma unroll
    for (int c = 0; c < 4; c++) {
        if (c < nch) {
            sc[c] = fast_exp(m[c] - M);
            L += sc[c] * l[c];
        }
    }

    float4 acc[2] = {};
#pragma unroll
    for (int c = 0; c < 4; c++) {
        if (c < nch) {
            const float* P = g_part + (slot0 + c) * (64 * 64) + (size_t)row * 64 + cg;
            float wgt = sc[c];
#pragma unroll
            for (int i = 0; i < 2; i++) {
                float4 v = *(const float4*)&P[4 * i];
                acc[i].x = fmaf(wgt, v.x, acc[i].x);
                acc[i].y = fmaf(wgt, v.y, acc[i].y);
                acc[i].z = fmaf(wgt, v.z, acc[i].z);
                acc[i].w = fmaf(wgt, v.w, acc[i].w);
            }
        }
    }

    float invL = 1.f / L;
    size_t o = ((size_t)b * TSEQ + qt * QT + row) * DDIM + cg;
#pragma unroll
    for (int i = 0; i < 2; i++) {
        *(float4*)&out[o + 4 * i] = make_float4(acc[i].x * invL, acc[i].y * invL,
                                                acc[i].z * invL, acc[i].w * invL);
    }
}

// ---------------------------------------------------------------------------
// Launch
// ---------------------------------------------------------------------------
extern "C" void kernel_launch(void* const* d_in, const int* in_sizes, int n_in,
                              void* d_out, int out_size)
{
    const float* x  = (const float*)d_in[0];
    const float* Wk = (const float*)d_in[1];
    const float* Wq = (const float*)d_in[2];
    const float* Wv = (const float*)d_in[3];
    float* out = (float*)d_out;

    cudaFuncSetAttribute(proj_mma,
                         cudaFuncAttributeMaxDynamicSharedMemorySize, PROJ_SMEM);

    conv_w<<<192, 256>>>(Wq, Wk, Wv);
    proj_mma<<<NROWS / 128, 512, PROJ_SMEM>>>(x);
    attn_split<<<dim3(NJOB, BSZ), 128>>>(out);
    attn_merge<<<dim3(24, BSZ), 512>>>(out);
}

// round 11
// speedup vs baseline: 1.1507x; 1.1507x over previous
#include <cuda_runtime.h>
#include <cuda_fp16.h>

#define NROWS 16384   // B*T
#define EDIM  1024
#define DDIM  64
#define BSZ   8
#define TSEQ  2048
#define QT    64      // attention q-tile rows
#define KT    64      // attention kv-tile rows
#define CKT   8       // kv tiles per chunk (512 keys)
#define NJOB  80      // jobs per batch = sum ceil((qt+1)/8), qt=0..31

// Projected tensors, fp16. q pre-scaled by 0.125. v stored transposed
// per batch: g_vt[b][d][t].
__device__ __align__(16) __half g_qh[NROWS * DDIM];
__device__ __align__(16) __half g_kh[NROWS * DDIM];
__device__ __align__(16) __half g_vt[BSZ * DDIM * TSEQ];

// Weights converted to fp16 once: [w][64][1024], w in {q,k,v}
__device__ __align__(16) __half g_wh[3 * DDIM * EDIM];

// Split-KV partials: [b][qt][chunk] -> unnormalized O (64x64), row m, row l
__device__ float g_part[(size_t)BSZ * 32 * 4 * 64 * 64];   // 16.8 MB
__device__ float g_pm[BSZ * 32 * 4 * 64];
__device__ float g_pl[BSZ * 32 * 4 * 64];

// ---------------------------------------------------------------------------
// helpers
// ---------------------------------------------------------------------------
__device__ __forceinline__ unsigned packh2(float lo, float hi) {
    __half2 h = __floats2half2_rn(lo, hi);
    return *reinterpret_cast<unsigned*>(&h);
}

__device__ __forceinline__ void mma16(float c[4],
                                      unsigned a0, unsigned a1,
                                      unsigned a2, unsigned a3,
                                      unsigned b0, unsigned b1) {
    asm volatile(
        "mma.sync.aligned.m16n8k16.row.col.f32.f16.f16.f32 "
        "{%0,%1,%2,%3},{%4,%5,%6,%7},{%8,%9},{%0,%1,%2,%3};\n"
        : "+f"(c[0]), "+f"(c[1]), "+f"(c[2]), "+f"(c[3])
        : "r"(a0), "r"(a1), "r"(a2), "r"(a3), "r"(b0), "r"(b1));
}

__device__ __forceinline__ void cpa16(void* dst_smem, const void* src) {
    unsigned d = (unsigned)__cvta_generic_to_shared(dst_smem);
    asm volatile("cp.async.cg.shared.global [%0], [%1], 16;\n"
                 :: "r"(d), "l"(src));
}
__device__ __forceinline__ void cpa_commit() {
    asm volatile("cp.async.commit_group;\n" ::: "memory");
}
template <int N>
__device__ __forceinline__ void cpa_wait() {
    asm volatile("cp.async.wait_group %0;\n" :: "n"(N) : "memory");
}

// exp(x) for x <= ~1, FMA-pipe only. deg-5 poly, rel err < 3e-6.
__device__ __forceinline__ float fast_exp(float x) {
    float t = x * 1.4426950408889634f;
    t = fmaxf(t, -126.0f);
    float tr = t + 12582912.0f;
    float fl = tr - 12582912.0f;
    float f  = t - fl;
    float p = 1.3333558146e-3f;
    p = fmaf(p, f, 9.6181291076e-3f);
    p = fmaf(p, f, 5.5504108664e-2f);
    p = fmaf(p, f, 2.4022650696e-1f);
    p = fmaf(p, f, 6.9314718056e-1f);
    p = fmaf(p, f, 1.0f);
    int n = __float_as_int(tr) - 0x4B400000;
    float s = __int_as_float((n + 127) << 23);
    return p * s;
}

// ---------------------------------------------------------------------------
// Weight conversion: fp32 -> fp16, once.
// ---------------------------------------------------------------------------
__global__ __launch_bounds__(256) void conv_w(
    const float* __restrict__ Wq,
    const float* __restrict__ Wk,
    const float* __restrict__ Wv)
{
    int idx = blockIdx.x * blockDim.x + threadIdx.x;   // float4 index
    int w   = idx >> 14;
    int rem = idx & 16383;
    const float* W = (w == 0) ? Wq : (w == 1) ? Wk : Wv;
    float4 v = *(const float4*)&W[rem * 4];
    __half2 h0 = __floats2half2_rn(v.x, v.y);
    __half2 h1 = __floats2half2_rn(v.z, v.w);
    uint2 u = make_uint2(*(unsigned*)&h0, *(unsigned*)&h1);
    *(uint2*)&g_wh[(size_t)w * DDIM * EDIM + rem * 4] = u;
}

// ---------------------------------------------------------------------------
// Merged projection GEMM (R6-proven shape + fp16 W + K-chunk 64).
// Block = 128-row x-slab, 256 threads, 8 warps: 4(m) x 2(n), warptile
// 32x32 per output. 2-stage cp.async, barrier/prefetch/wait/barrier
// per 64-wide K chunk (16 chunks -> half the sync count of R6).
// Stage = 128x68 f32 (x) + 3x64x72 f16 (W) = 62464 B; 2 stages = 124928 B.
// Grid = 128 blocks.
// ---------------------------------------------------------------------------
#define PROJ_XS_F    (128 * 68)                           // floats
#define PROJ_WS_H    (3 * 64 * 72)                        // halves
#define PROJ_STAGE_B (PROJ_XS_F * 4 + PROJ_WS_H * 2)      // 62464 bytes
#define PROJ_SMEM    (2 * PROJ_STAGE_B)                   // 124928

__global__ __launch_bounds__(256, 1) void proj_mma(
    const float* __restrict__ x)
{
    extern __shared__ char dynb[];

    const int tid  = threadIdx.x;
    const int lane = tid & 31;
    const int wid  = tid >> 5;
    const int wm   = wid & 3;       // 4 m-warps (32 rows each)
    const int wn   = wid >> 2;      // 2 n-warps (32 cols each)
    const int r    = lane >> 2;
    const int cq   = lane & 3;
    const int m0   = blockIdx.x * 128;

    auto prefetch = [&](int kc, int s) {
        char* stage = dynb + (size_t)s * PROJ_STAGE_B;
        float  (*xs)[68]     = (float(*)[68])stage;
        __half (*ws)[64][72] = (__half(*)[64][72])(stage + PROJ_XS_F * 4);
        int k0 = kc * 64;
#pragma unroll
        for (int i = 0; i < 8; i++) {
            int slot = tid + i * 256;        // 2048 chunks (128 rows x 16)
            int m = slot >> 4, j = slot & 15;
            cpa16(&xs[m][4 * j], &x[(size_t)(m0 + m) * EDIM + k0 + 4 * j]);
        }
#pragma unroll
        for (int i = 0; i < 6; i++) {
            int slot = tid + i * 256;        // 1536 chunks (3x64 rows x 8)
            int w = slot >> 9, rem = slot & 511;
            int d = rem >> 3, j = rem & 7;
            cpa16(&ws[w][d][8 * j],
                  &g_wh[(size_t)w * DDIM * EDIM + (size_t)d * EDIM + k0 + 8 * j]);
        }
        cpa_commit();
    };

    float acc[3][2][4][4] = {};   // [output][mt][nt][reg]

    prefetch(0, 0);
    for (int kc = 0; kc < 16; kc++) {
        const int s = kc & 1;
        __syncthreads();                      // stage s^1 fully consumed
        if (kc + 1 < 16) { prefetch(kc + 1, s ^ 1); cpa_wait<1>(); }
        else             { cpa_wait<0>(); }
        __syncthreads();                      // stage s visible

        char* stage = dynb + (size_t)s * PROJ_STAGE_B;
        float  (*xs)[68]     = (float(*)[68])stage;
        __half (*ws)[64][72] = (__half(*)[64][72])(stage + PROJ_XS_F * 4);

#pragma unroll
        for (int ks = 0; ks < 4; ks++) {
            int k = ks * 16;
            unsigned a[2][4];
#pragma unroll
            for (int mt = 0; mt < 2; mt++) {
                int rb = wm * 32 + mt * 16;
                float2 x0 = *(float2*)&xs[rb + r][k + 2 * cq];
                float2 x1 = *(float2*)&xs[rb + r + 8][k + 2 * cq];
                float2 x2 = *(float2*)&xs[rb + r][k + 2 * cq + 8];
                float2 x3 = *(float2*)&xs[rb + r + 8][k + 2 * cq + 8];
                a[mt][0] = packh2(x0.x, x0.y);
                a[mt][1] = packh2(x1.x, x1.y);
                a[mt][2] = packh2(x2.x, x2.y);
                a[mt][3] = packh2(x3.x, x3.y);
            }
#pragma unroll
            for (int w = 0; w < 3; w++)
#pragma unroll
                for (int nt = 0; nt < 4; nt++) {
                    int nb = wn * 32 + nt * 8 + r;
                    unsigned b0 = *(const unsigned*)&ws[w][nb][k + 2 * cq];
                    unsigned b1 = *(const unsigned*)&ws[w][nb][k + 2 * cq + 8];
                    mma16(acc[w][0][nt], a[0][0], a[0][1], a[0][2], a[0][3], b0, b1);
                    mma16(acc[w][1][nt], a[1][0], a[1][1], a[1][2], a[1][3], b0, b1);
                }
        }
    }

    // epilogue: q (scaled), k natural fp16; v transposed fp16
#pragma unroll
    for (int mt = 0; mt < 2; mt++)
#pragma unroll
        for (int nt = 0; nt < 4; nt++) {
            int row = m0 + wm * 32 + mt * 16 + r;
            int col = wn * 32 + nt * 8 + 2 * cq;
            {
                float* a = acc[0][mt][nt];
                *(__half2*)&g_qh[(size_t)row * DDIM + col] =
                    __floats2half2_rn(a[0] * 0.125f, a[1] * 0.125f);
                *(__half2*)&g_qh[(size_t)(row + 8) * DDIM + col] =
                    __floats2half2_rn(a[2] * 0.125f, a[3] * 0.125f);
            }
            {
                float* a = acc[1][mt][nt];
                *(__half2*)&g_kh[(size_t)row * DDIM + col] =
                    __floats2half2_rn(a[0], a[1]);
                *(__half2*)&g_kh[(size_t)(row + 8) * DDIM + col] =
                    __floats2half2_rn(a[2], a[3]);
            }
            {
                float* a = acc[2][mt][nt];
                int bb = row >> 11;
                int tt = row & 2047;
                size_t vb = (size_t)bb * DDIM * TSEQ;
                g_vt[vb + (size_t)col * TSEQ + tt]           = __float2half_rn(a[0]);
                g_vt[vb + (size_t)(col + 1) * TSEQ + tt]     = __float2half_rn(a[1]);
                g_vt[vb + (size_t)col * TSEQ + tt + 8]       = __float2half_rn(a[2]);
                g_vt[vb + (size_t)(col + 1) * TSEQ + tt + 8] = __float2half_rn(a[3]);
            }
        }
}

// ---------------------------------------------------------------------------
// Split-KV flash attention (R6-proven loop: 2-stage, 2 barriers/tile).
// Job = (batch, q-tile, kv-chunk of <=8 KT-tiles). 640 blocks.
// ---------------------------------------------------------------------------
__global__ __launch_bounds__(128, 4) void attn_split(float* __restrict__ out)
{
    __shared__ __align__(16) __half Ks[2][KT][72];
    __shared__ __align__(16) __half Vt[2][DDIM][72];

    const int tid  = threadIdx.x;
    const int lane = tid & 31;
    const int w    = tid >> 5;
    const int r    = lane >> 2;
    const int cq   = lane & 3;
    const int b    = blockIdx.y;

    // job decode (reversed so 8-tile chunks launch first)
    const int j = NJOB - 1 - blockIdx.x;
    int qt, ck;
    if (j < 8)       { qt = j;                   ck = 0; }
    else if (j < 24) { qt = 8  + ((j - 8)  >> 1); ck = (j - 8)  & 1; }
    else if (j < 48) { qt = 16 + (j - 24) / 3;    ck = (j - 24) % 3; }
    else             { qt = 24 + ((j - 48) >> 2); ck = (j - 48) & 3; }
    const int nch  = qt / CKT + 1;
    const int kbeg = ck * CKT;
    const int kend = min(kbeg + CKT, qt + 1);

    const int q0 = qt * QT;
    const size_t base  = (size_t)b * TSEQ * DDIM;
    const size_t vbase = (size_t)b * DDIM * TSEQ;

    auto prefetch = [&](int kt, int s) {
        int k0 = kt * KT;
#pragma unroll
        for (int i = 0; i < 4; i++) {
            int slot = tid + i * 128;
            int m = slot >> 3, jj = slot & 7;
            cpa16(&Ks[s][m][8 * jj], &g_kh[base + (size_t)(k0 + m) * DDIM + 8 * jj]);
            cpa16(&Vt[s][m][8 * jj], &g_vt[vbase + (size_t)m * TSEQ + k0 + 8 * jj]);
        }
        cpa_commit();
    };

    // Q fragments (fp16, pre-scaled)
    unsigned qa[4][4];
    {
        const __half* q0p = &g_qh[base + (size_t)(q0 + 16 * w + r) * DDIM];
        const __half* q1p = q0p + 8 * DDIM;
#pragma unroll
        for (int kc = 0; kc < 4; kc++) {
            int c = 16 * kc + 2 * cq;
            qa[kc][0] = *(const unsigned*)&q0p[c];
            qa[kc][1] = *(const unsigned*)&q1p[c];
            qa[kc][2] = *(const unsigned*)&q0p[c + 8];
            qa[kc][3] = *(const unsigned*)&q1p[c + 8];
        }
    }

    float O[8][4] = {};
    float mA = -1e30f, mB = -1e30f, lA = 0.f, lB = 0.f;

    prefetch(kbeg, 0);

    for (int kt = kbeg; kt < kend; kt++) {
        const int s  = (kt - kbeg) & 1;
        const int k0 = kt * KT;
        __syncthreads();
        if (kt + 1 < kend) { prefetch(kt + 1, s ^ 1); cpa_wait<1>(); }
        else               { cpa_wait<0>(); }
        __syncthreads();

        // ---- S = Q * K^T ----
        float sacc[8][4] = {};
#pragma unroll
        for (int kc = 0; kc < 4; kc++) {
#pragma unroll
            for (int nt = 0; nt < 8; nt++) {
                unsigned b0 = *(const unsigned*)&Ks[s][nt * 8 + r][16 * kc + 2 * cq];
                unsigned b1 = *(const unsigned*)&Ks[s][nt * 8 + r][16 * kc + 2 * cq + 8];
                mma16(sacc[nt], qa[kc][0], qa[kc][1], qa[kc][2], qa[kc][3], b0, b1);
            }
        }

        // ---- causal mask (diagonal tile only) ----
        if (kt == qt) {
            int rowg = q0 + 16 * w + r;
#pragma unroll
            for (int nt = 0; nt < 8; nt++) {
                int col = k0 + nt * 8 + 2 * cq;
                if (col     > rowg)     sacc[nt][0] = -1e30f;
                if (col + 1 > rowg)     sacc[nt][1] = -1e30f;
                if (col     > rowg + 8) sacc[nt][2] = -1e30f;
                if (col + 1 > rowg + 8) sacc[nt][3] = -1e30f;
            }
        }

        // ---- warp-local online softmax; P packed in registers ----
        unsigned phA[8], phB[8];
        {
            float pmA = -1e30f, pmB = -1e30f;
#pragma unroll
            for (int nt = 0; nt < 8; nt++) {
                pmA = fmaxf(pmA, fmaxf(sacc[nt][0], sacc[nt][1]));
                pmB = fmaxf(pmB, fmaxf(sacc[nt][2], sacc[nt][3]));
            }
            pmA = fmaxf(pmA, __shfl_xor_sync(0xffffffffu, pmA, 1));
            pmA = fmaxf(pmA, __shfl_xor_sync(0xffffffffu, pmA, 2));
            pmB = fmaxf(pmB, __shfl_xor_sync(0xffffffffu, pmB, 1));
            pmB = fmaxf(pmB, __shfl_xor_sync(0xffffffffu, pmB, 2));
            float nmA = fmaxf(mA, pmA), nmB = fmaxf(mB, pmB);
            float alA = fast_exp(mA - nmA), alB = fast_exp(mB - nmB);
            mA = nmA; mB = nmB;

            float sA = 0.f, sB = 0.f;
#pragma unroll
            for (int nt = 0; nt < 8; nt++) {
                float p0 = fast_exp(sacc[nt][0] - nmA);
                float p1 = fast_exp(sacc[nt][1] - nmA);
                float p2 = fast_exp(sacc[nt][2] - nmB);
                float p3 = fast_exp(sacc[nt][3] - nmB);
                sA += p0 + p1; sB += p2 + p3;
                phA[nt] = packh2(p0, p1);
                phB[nt] = packh2(p2, p3);
            }
            sA += __shfl_xor_sync(0xffffffffu, sA, 1);
            sA += __shfl_xor_sync(0xffffffffu, sA, 2);
            sB += __shfl_xor_sync(0xffffffffu, sB, 1);
            sB += __shfl_xor_sync(0xffffffffu, sB, 2);
            lA = lA * alA + sA;
            lB = lB * alB + sB;
#pragma unroll
            for (int nt = 0; nt < 8; nt++) {
                O[nt][0] *= alA; O[nt][1] *= alA;
                O[nt][2] *= alB; O[nt][3] *= alB;
            }
        }

        // ---- O += P * V ----
#pragma unroll
        for (int kc = 0; kc < 4; kc++) {
            unsigned a0 = phA[2 * kc],     a1 = phB[2 * kc];
            unsigned a2 = phA[2 * kc + 1], a3 = phB[2 * kc + 1];
#pragma unroll
            for (int nt = 0; nt < 8; nt++) {
                unsigned b0 = *(const unsigned*)&Vt[s][nt * 8 + r][16 * kc + 2 * cq];
                unsigned b1 = *(const unsigned*)&Vt[s][nt * 8 + r][16 * kc + 2 * cq + 8];
                mma16(O[nt], a0, a1, a2, a3, b0, b1);
            }
        }
    }

    // ---- epilogue ----
    if (nch == 1) {
        float ilA = 1.f / lA, ilB = 1.f / lB;
        int rowg = q0 + 16 * w + r;
#pragma unroll
        for (int nt = 0; nt < 8; nt++) {
            int col = nt * 8 + 2 * cq;
            *(float2*)&out[base + (size_t)rowg * DDIM + col] =
                make_float2(O[nt][0] * ilA, O[nt][1] * ilA);
            *(float2*)&out[base + (size_t)(rowg + 8) * DDIM + col] =
                make_float2(O[nt][2] * ilB, O[nt][3] * ilB);
        }
    } else {
        const size_t slot = ((size_t)b * 32 + qt) * 4 + ck;
        float* P = g_part + slot * (64 * 64);
        int rowL = 16 * w + r;
#pragma unroll
        for (int nt = 0; nt < 8; nt++) {
            int col = nt * 8 + 2 * cq;
            *(float2*)&P[(size_t)rowL * 64 + col]       = make_float2(O[nt][0], O[nt][1]);
            *(float2*)&P[(size_t)(rowL + 8) * 64 + col] = make_float2(O[nt][2], O[nt][3]);
        }
        if (cq == 0) {
            g_pm[slot * 64 + rowL]     = mA;
            g_pl[slot * 64 + rowL]     = lA;
            g_pm[slot * 64 + rowL + 8] = mB;
            g_pl[slot * 64 + rowL + 8] = lB;
        }
    }
}

// ---------------------------------------------------------------------------
// Merge kernel: combine 2..4 KV-chunk partials for q-tiles qt >= 8.
// Grid (24, 8), 512 threads: thread owns one row x 8 d-cols.
// ---------------------------------------------------------------------------
__global__ __launch_bounds__(512) void attn_merge(float* __restrict__ out)
{
    const int qt  = 8 + blockIdx.x;
    const int b   = blockIdx.y;
    const int nch = qt / CKT + 1;
    const int tid = threadIdx.x;
    const int row = tid >> 3;
    const int cg  = (tid & 7) * 8;

    const size_t slot0 = ((size_t)b * 32 + qt) * 4;

    float m[4], l[4];
    float M = -1e30f;
#pragma unroll
    for (int c = 0; c < 4; c++) {
        if (c < nch) {
            m[c] = g_pm[(slot0 + c) * 64 + row];
            l[c] = g_pl[(slot0 + c) * 64 + row];
            M = fmaxf(M, m[c]);
        }
    }
    float L = 0.f, sc[4];
#pragma unroll
    for (int c = 0; c < 4; c++) {
        if (c < nch) {
            sc[c] = fast_exp(m[c] - M);
            L += sc[c] * l[c];
        }
    }

    float4 acc[2] = {};
#pragma unroll
    for (int c = 0; c < 4; c++) {
        if (c < nch) {
            const float* P = g_part + (slot0 + c) * (64 * 64) + (size_t)row * 64 + cg;
            float wgt = sc[c];
#pragma unroll
            for (int i = 0; i < 2; i++) {
                float4 v = *(const float4*)&P[4 * i];
                acc[i].x = fmaf(wgt, v.x, acc[i].x);
                acc[i].y = fmaf(wgt, v.y, acc[i].y);
                acc[i].z = fmaf(wgt, v.z, acc[i].z);
                acc[i].w = fmaf(wgt, v.w, acc[i].w);
            }
        }
    }

    float invL = 1.f / L;
    size_t o = ((size_t)b * TSEQ + qt * QT + row) * DDIM + cg;
#pragma unroll
    for (int i = 0; i < 2; i++) {
        *(float4*)&out[o + 4 * i] = make_float4(acc[i].x * invL, acc[i].y * invL,
                                                acc[i].z * invL, acc[i].w * invL);
    }
}

// ---------------------------------------------------------------------------
// Launch
// ---------------------------------------------------------------------------
extern "C" void kernel_launch(void* const* d_in, const int* in_sizes, int n_in,
                              void* d_out, int out_size)
{
    const float* x  = (const float*)d_in[0];
    const float* Wk = (const float*)d_in[1];
    const float* Wq = (const float*)d_in[2];
    const float* Wv = (const float*)d_in[3];
    float* out = (float*)d_out;

    cudaFuncSetAttribute(proj_mma,
                         cudaFuncAttributeMaxDynamicSharedMemorySize, PROJ_SMEM);

    conv_w<<<192, 256>>>(Wq, Wk, Wv);
    proj_mma<<<NROWS / 128, 256, PROJ_SMEM>>>(x);
    attn_split<<<dim3(NJOB, BSZ), 128>>>(out);
    attn_merge<<<dim3(24, BSZ), 512>>>(out);
}